// round 12
// baseline (speedup 1.0000x reference)
#include <cuda_runtime.h>
#include <cuda_bf16.h>
#include <cuda_fp16.h>
#include <math.h>
#include <stdint.h>

// ---------------- problem constants ----------------
#define BB   2
#define TT   2048
#define DD   1024
#define NHH  16
#define HDD  64
#define FFD  4096
#define NLL  2
#define VV   32000
#define MM   (BB*TT)          // 4096 rows
#define EPSF 1.1920929e-07f

// ---------------- scratch (device globals; no allocation allowed) ------------
__device__ float g_h  [MM * DD];        // residual stream (fp32)
__device__ float g_fg [MM * FFD];       // gate (silu applied, fp32)
__device__ __nv_bfloat16 g_nh [MM * DD];      // rmsnorm out hi/lo planes
__device__ __nv_bfloat16 g_nl [MM * DD];
__device__ __nv_bfloat16 g_qh3[MM * 3 * DD];  // qkv hi/lo planes
__device__ __nv_bfloat16 g_ql3[MM * 3 * DD];
__device__ __nv_bfloat16 g_ah [MM * DD];      // attention out hi/lo
__device__ __nv_bfloat16 g_al [MM * DD];
__device__ __nv_bfloat16 g_fgh[MM * FFD];     // gate*up hi/lo
__device__ __nv_bfloat16 g_fgl[MM * FFD];
__device__ __nv_bfloat16 g_wh [VV * DD];      // split weights (max = head)
__device__ __nv_bfloat16 g_wl [VV * DD];

// ---------------- small helpers ----------------
__device__ __forceinline__ uint32_t s2u(const void* p) {
    uint32_t a;
    asm("{ .reg .u64 t; cvta.to.shared.u64 t, %1; cvt.u32.u64 %0, t; }" : "=r"(a) : "l"(p));
    return a;
}
__device__ __forceinline__ void bsplit(float x, __nv_bfloat16& hi, __nv_bfloat16& lo) {
    hi = __float2bfloat16(x);
    lo = __float2bfloat16(x - __bfloat162float(hi));
}
__device__ __forceinline__ void bsplit_pack(float x, float y, uint32_t& hp, uint32_t& lp) {
    __nv_bfloat16 hx, lx, hy, ly;
    bsplit(x, hx, lx); bsplit(y, hy, ly);
    __nv_bfloat162 h2 = __halves2bfloat162(hx, hy);
    __nv_bfloat162 l2 = __halves2bfloat162(lx, ly);
    hp = *(uint32_t*)&h2; lp = *(uint32_t*)&l2;
}
__device__ __forceinline__ void hsplit_pack(float x, float y, uint32_t& hp, uint32_t& lp) {
    __half hx = __float2half_rn(x);
    __half hy = __float2half_rn(y);
    __half lx = __float2half_rn(x - __half2float(hx));
    __half ly = __float2half_rn(y - __half2float(hy));
    __half2 h2 = __halves2half2(hx, hy);
    __half2 l2 = __halves2half2(lx, ly);
    hp = *(uint32_t*)&h2; lp = *(uint32_t*)&l2;
}
__device__ __forceinline__ void mma16(float* c, const uint32_t* a, const uint32_t* b) {
    asm volatile(
        "mma.sync.aligned.m16n8k16.row.col.f32.bf16.bf16.f32 "
        "{%0,%1,%2,%3}, {%4,%5,%6,%7}, {%8,%9}, {%0,%1,%2,%3};"
        : "+f"(c[0]), "+f"(c[1]), "+f"(c[2]), "+f"(c[3])
        : "r"(a[0]), "r"(a[1]), "r"(a[2]), "r"(a[3]), "r"(b[0]), "r"(b[1]));
}
__device__ __forceinline__ void mma16f(float* c, const uint32_t* a, const uint32_t* b) {
    asm volatile(
        "mma.sync.aligned.m16n8k16.row.col.f32.f16.f16.f32 "
        "{%0,%1,%2,%3}, {%4,%5,%6,%7}, {%8,%9}, {%0,%1,%2,%3};"
        : "+f"(c[0]), "+f"(c[1]), "+f"(c[2]), "+f"(c[3])
        : "r"(a[0]), "r"(a[1]), "r"(a[2]), "r"(a[3]), "r"(b[0]), "r"(b[1]));
}

// ---------------- embedding gather ----------------
__global__ void embed_kernel(const int* __restrict__ x,
                             const float* __restrict__ emb,
                             float* __restrict__ h)
{
    int row = blockIdx.x;
    int t   = threadIdx.x;                // 256 threads, float4 each
    int id  = x[row];
    const float4* src = (const float4*)(emb + (size_t)id * DD);
    float4*       dst = (float4*)(h + (size_t)row * DD);
    dst[t] = src[t];
}

// ---------------- RMSNorm -> hi/lo bf16 planes ----------------
__global__ void rmsnorm_kernel(const float* __restrict__ in,
                               const float* __restrict__ w,
                               __nv_bfloat16* __restrict__ oh,
                               __nv_bfloat16* __restrict__ ol)
{
    int row = blockIdx.x;
    int t   = threadIdx.x;
    const float4* r4 = (const float4*)(in + (size_t)row * DD);
    float4 v = r4[t];
    float ss = v.x*v.x + v.y*v.y + v.z*v.z + v.w*v.w;
    #pragma unroll
    for (int o = 16; o; o >>= 1) ss += __shfl_xor_sync(0xffffffffu, ss, o);
    __shared__ float red[8];
    if ((t & 31) == 0) red[t >> 5] = ss;
    __syncthreads();
    __shared__ float scale_sh;
    if (t == 0) {
        float s = 0.f;
        #pragma unroll
        for (int i = 0; i < 8; i++) s += red[i];
        scale_sh = rsqrtf(s / (float)DD + EPSF);
    }
    __syncthreads();
    float sc = scale_sh;
    const float4* w4 = (const float4*)w;
    float4 wv = w4[t];
    uint32_t h0, l0, h1, l1;
    bsplit_pack(v.x * sc * wv.x, v.y * sc * wv.y, h0, l0);
    bsplit_pack(v.z * sc * wv.z, v.w * sc * wv.w, h1, l1);
    uint32_t* ph = (uint32_t*)(oh + (size_t)row * DD);
    uint32_t* pl = (uint32_t*)(ol + (size_t)row * DD);
    ph[2*t] = h0; ph[2*t+1] = h1;
    pl[2*t] = l0; pl[2*t+1] = l1;
}

// ---------------- RMSNorm -> single fp16 plane (final norm for head) ---------
__global__ void rmsnorm_f16_kernel(const float* __restrict__ in,
                                   const float* __restrict__ w,
                                   __half* __restrict__ oh)
{
    int row = blockIdx.x;
    int t   = threadIdx.x;
    const float4* r4 = (const float4*)(in + (size_t)row * DD);
    float4 v = r4[t];
    float ss = v.x*v.x + v.y*v.y + v.z*v.z + v.w*v.w;
    #pragma unroll
    for (int o = 16; o; o >>= 1) ss += __shfl_xor_sync(0xffffffffu, ss, o);
    __shared__ float red[8];
    if ((t & 31) == 0) red[t >> 5] = ss;
    __syncthreads();
    __shared__ float scale_sh;
    if (t == 0) {
        float s = 0.f;
        #pragma unroll
        for (int i = 0; i < 8; i++) s += red[i];
        scale_sh = rsqrtf(s / (float)DD + EPSF);
    }
    __syncthreads();
    float sc = scale_sh;
    const float4* w4 = (const float4*)w;
    float4 wv = w4[t];
    __half2 a = __halves2half2(__float2half_rn(v.x * sc * wv.x),
                               __float2half_rn(v.y * sc * wv.y));
    __half2 b = __halves2half2(__float2half_rn(v.z * sc * wv.z),
                               __float2half_rn(v.w * sc * wv.w));
    uint32_t* ph = (uint32_t*)(oh + (size_t)row * DD);
    ph[2*t]   = *(uint32_t*)&a;
    ph[2*t+1] = *(uint32_t*)&b;
}

// ---------------- weight split pass (fp32 -> hi/lo bf16 planes) --------------
__global__ void wsplit_kernel(const float* __restrict__ in,
                              __nv_bfloat16* __restrict__ oh,
                              __nv_bfloat16* __restrict__ ol, int n4)
{
    int i = blockIdx.x * blockDim.x + threadIdx.x;
    if (i < n4) {
        float4 v = ((const float4*)in)[i];
        uint32_t h0, l0, h1, l1;
        bsplit_pack(v.x, v.y, h0, l0);
        bsplit_pack(v.z, v.w, h1, l1);
        ((uint32_t*)oh)[2*i] = h0; ((uint32_t*)oh)[2*i+1] = h1;
        ((uint32_t*)ol)[2*i] = l0; ((uint32_t*)ol)[2*i+1] = l1;
    }
}

// ---------------- weight split pass (fp32 -> hi/lo fp16 planes) --------------
__global__ void wsplit16_kernel(const float* __restrict__ in,
                                __half* __restrict__ oh,
                                __half* __restrict__ ol, int n4)
{
    int i = blockIdx.x * blockDim.x + threadIdx.x;
    if (i < n4) {
        float4 v = ((const float4*)in)[i];
        uint32_t h0, l0, h1, l1;
        hsplit_pack(v.x, v.y, h0, l0);
        hsplit_pack(v.z, v.w, h1, l1);
        ((uint32_t*)oh)[2*i] = h0; ((uint32_t*)oh)[2*i+1] = h1;
        ((uint32_t*)ol)[2*i] = l0; ((uint32_t*)ol)[2*i+1] = l1;
    }
}

// ============================================================================
// bf16x3 GEMM (R7-validated mainloop): C = (Ahi+Alo)(Whi+Wlo)^T (+bias)(+epi)
// CTA tile 128x128, K-chunk 32, 3-stage cp.async, 8 warps (4x2),
// warp tile 32(M)x64(N). XOR-swizzled smem, scalar LDS fragment loads.
// EPI: 0 bias | 1 bias+res | 2 bias+silu | 3 bias,*gate,split-out | 4 bias,split-out
// ============================================================================
#define SWZ(r,j)   ((r)*16 + ((j) ^ ((((r)>>1)&3)<<2)))
#define STG_U32    8192                        // 4 planes * 128 rows * 16 b32
#define GEMM_SMEM  (3 * STG_U32 * 4)           // 98304 bytes

template<int EPI>
__global__ void __launch_bounds__(256, 2)
gemm_bf3(const __nv_bfloat16* __restrict__ Ahi, const __nv_bfloat16* __restrict__ Alo,
         const __nv_bfloat16* __restrict__ Whi, const __nv_bfloat16* __restrict__ Wlo,
         const float* __restrict__ bias, const float* __restrict__ res,
         float* __restrict__ C,
         __nv_bfloat16* __restrict__ Ch, __nv_bfloat16* __restrict__ Cl,
         int N, int K)
{
    extern __shared__ uint32_t smu[];
    const int tid  = threadIdx.x;
    const int wid  = tid >> 5;
    const int lane = tid & 31;
    const int g    = lane >> 2;     // 0..7
    const int t    = lane & 3;      // 0..3
    const int wm   = (wid >> 1) * 32;   // warp M offset
    const int wn   = (wid & 1) * 64;    // warp N offset

    const __nv_bfloat16* Agh = Ahi + (size_t)blockIdx.y * 128 * K;
    const __nv_bfloat16* Agl = Alo + (size_t)blockIdx.y * 128 * K;
    const __nv_bfloat16* Wgh = Whi + (size_t)blockIdx.x * 128 * K;
    const __nv_bfloat16* Wgl = Wlo + (size_t)blockIdx.x * 128 * K;
    const int NC = K >> 5;              // chunks of K=32

    auto fill = [&](int c) {
        uint32_t* st = smu + (c % 3) * STG_U32;
        const __nv_bfloat16* s0 = Agh + c * 32;
        const __nv_bfloat16* s1 = Agl + c * 32;
        const __nv_bfloat16* s2 = Wgh + c * 32;
        const __nv_bfloat16* s3 = Wgl + c * 32;
        #pragma unroll
        for (int i = 0; i < 2; i++) {
            int lin = tid + i * 256;            // 0..511
            int r = lin >> 2, q = lin & 3;      // row, 16B-quarter
            uint32_t doff = SWZ(r, q * 4);      // u32 index within plane
            size_t soff = (size_t)r * K + q * 8;
            uint32_t d0 = s2u(st + doff);       // byte address; planes +8192B
            asm volatile("cp.async.cg.shared.global [%0], [%1], 16;" :: "r"(d0),         "l"(s0 + soff));
            asm volatile("cp.async.cg.shared.global [%0], [%1], 16;" :: "r"(d0 + 8192),  "l"(s1 + soff));
            asm volatile("cp.async.cg.shared.global [%0], [%1], 16;" :: "r"(d0 + 16384), "l"(s2 + soff));
            asm volatile("cp.async.cg.shared.global [%0], [%1], 16;" :: "r"(d0 + 24576), "l"(s3 + soff));
        }
    };

    float acc[2][8][4] = {};

    fill(0); asm volatile("cp.async.commit_group;" ::: "memory");
    fill(1); asm volatile("cp.async.commit_group;" ::: "memory");

    for (int c = 0; c < NC; c++) {
        asm volatile("cp.async.wait_group 1;" ::: "memory");
        __syncthreads();
        if (c + 2 < NC) fill(c + 2);
        asm volatile("cp.async.commit_group;" ::: "memory");

        const uint32_t* st  = smu + (c % 3) * STG_U32;
        const uint32_t* sAh = st;
        const uint32_t* sAl = st + 2048;
        const uint32_t* sBh = st + 4096;
        const uint32_t* sBl = st + 6144;

        #pragma unroll
        for (int ks = 0; ks < 2; ks++) {
            const int j0 = ks * 8 + t;
            uint32_t ah[2][4], al[2][4];
            #pragma unroll
            for (int mt = 0; mt < 2; mt++) {
                int r0 = wm + mt * 16 + g, r1 = r0 + 8;
                ah[mt][0] = sAh[SWZ(r0, j0)];     ah[mt][1] = sAh[SWZ(r1, j0)];
                ah[mt][2] = sAh[SWZ(r0, j0 + 4)]; ah[mt][3] = sAh[SWZ(r1, j0 + 4)];
                al[mt][0] = sAl[SWZ(r0, j0)];     al[mt][1] = sAl[SWZ(r1, j0)];
                al[mt][2] = sAl[SWZ(r0, j0 + 4)]; al[mt][3] = sAl[SWZ(r1, j0 + 4)];
            }
            #pragma unroll
            for (int nt = 0; nt < 8; nt++) {
                int r = wn + nt * 8 + g;
                uint32_t bh[2] = { sBh[SWZ(r, j0)], sBh[SWZ(r, j0 + 4)] };
                uint32_t bl[2] = { sBl[SWZ(r, j0)], sBl[SWZ(r, j0 + 4)] };
                // term-major: chain spacing 2 instead of 1
                mma16(acc[0][nt], ah[0], bh);
                mma16(acc[1][nt], ah[1], bh);
                mma16(acc[0][nt], ah[0], bl);
                mma16(acc[1][nt], ah[1], bl);
                mma16(acc[0][nt], al[0], bh);
                mma16(acc[1][nt], al[1], bh);
            }
        }
    }

    // ---- epilogue ----
    const size_t rbase = (size_t)blockIdx.y * 128 + wm;
    const int    cbase = blockIdx.x * 128 + wn;
    #pragma unroll
    for (int mt = 0; mt < 2; mt++) {
        #pragma unroll
        for (int half = 0; half < 2; half++) {
            size_t row = rbase + mt * 16 + half * 8 + g;
            size_t rowoff = row * (size_t)N;
            #pragma unroll
            for (int nt = 0; nt < 8; nt++) {
                int col = cbase + nt * 8 + 2 * t;
                float v0 = acc[mt][nt][half * 2 + 0];
                float v1 = acc[mt][nt][half * 2 + 1];
                if (bias) {
                    v0 += __ldg(bias + col);
                    v1 += __ldg(bias + col + 1);
                }
                if (EPI == 1) {
                    float2 rv = *(const float2*)(res + rowoff + col);
                    v0 += rv.x; v1 += rv.y;
                }
                if (EPI == 2) {
                    v0 = v0 / (1.f + __expf(-v0));
                    v1 = v1 / (1.f + __expf(-v1));
                }
                if (EPI == 3 || EPI == 4) {
                    if (EPI == 3) {
                        float2 gv = *(const float2*)(res + rowoff + col);
                        v0 *= gv.x; v1 *= gv.y;
                    }
                    uint32_t hp, lp;
                    bsplit_pack(v0, v1, hp, lp);
                    *(uint32_t*)(Ch + rowoff + col) = hp;
                    *(uint32_t*)(Cl + rowoff + col) = lp;
                } else {
                    float2 ov; ov.x = v0; ov.y = v1;
                    *(float2*)(C + rowoff + col) = ov;
                }
            }
        }
    }
}

// ============================================================================
// fp16 2-term GEMM (head only): C = Ah * (Wh+Wl)^T
// A is single fp16 plane; W split hi/lo fp16. 3 smem planes per stage.
// Same tiling as gemm_bf3. Activation-rounding error ~1.4e-4 (output-only).
// ============================================================================
#define STG16_U32   6144                       // 3 planes * 2048 u32
#define GEMM16_SMEM (3 * STG16_U32 * 4)        // 73728 bytes

__global__ void __launch_bounds__(256, 2)
gemm_f16(const __half* __restrict__ A,
         const __half* __restrict__ Whi, const __half* __restrict__ Wlo,
         float* __restrict__ C, int N, int K)
{
    extern __shared__ uint32_t smu[];
    const int tid  = threadIdx.x;
    const int wid  = tid >> 5;
    const int lane = tid & 31;
    const int g    = lane >> 2;
    const int t    = lane & 3;
    const int wm   = (wid >> 1) * 32;
    const int wn   = (wid & 1) * 64;

    const __half* Ag  = A   + (size_t)blockIdx.y * 128 * K;
    const __half* Wgh = Whi + (size_t)blockIdx.x * 128 * K;
    const __half* Wgl = Wlo + (size_t)blockIdx.x * 128 * K;
    const int NC = K >> 5;

    auto fill = [&](int c) {
        uint32_t* st = smu + (c % 3) * STG16_U32;
        const __half* s0 = Ag  + c * 32;
        const __half* s1 = Wgh + c * 32;
        const __half* s2 = Wgl + c * 32;
        #pragma unroll
        for (int i = 0; i < 2; i++) {
            int lin = tid + i * 256;
            int r = lin >> 2, q = lin & 3;
            uint32_t doff = SWZ(r, q * 4);
            size_t soff = (size_t)r * K + q * 8;
            uint32_t d0 = s2u(st + doff);
            asm volatile("cp.async.cg.shared.global [%0], [%1], 16;" :: "r"(d0),         "l"(s0 + soff));
            asm volatile("cp.async.cg.shared.global [%0], [%1], 16;" :: "r"(d0 + 8192),  "l"(s1 + soff));
            asm volatile("cp.async.cg.shared.global [%0], [%1], 16;" :: "r"(d0 + 16384), "l"(s2 + soff));
        }
    };

    float acc[2][8][4] = {};

    fill(0); asm volatile("cp.async.commit_group;" ::: "memory");
    fill(1); asm volatile("cp.async.commit_group;" ::: "memory");

    for (int c = 0; c < NC; c++) {
        asm volatile("cp.async.wait_group 1;" ::: "memory");
        __syncthreads();
        if (c + 2 < NC) fill(c + 2);
        asm volatile("cp.async.commit_group;" ::: "memory");

        const uint32_t* st  = smu + (c % 3) * STG16_U32;
        const uint32_t* sA  = st;
        const uint32_t* sBh = st + 2048;
        const uint32_t* sBl = st + 4096;

        #pragma unroll
        for (int ks = 0; ks < 2; ks++) {
            const int j0 = ks * 8 + t;
            uint32_t af[2][4];
            #pragma unroll
            for (int mt = 0; mt < 2; mt++) {
                int r0 = wm + mt * 16 + g, r1 = r0 + 8;
                af[mt][0] = sA[SWZ(r0, j0)];     af[mt][1] = sA[SWZ(r1, j0)];
                af[mt][2] = sA[SWZ(r0, j0 + 4)]; af[mt][3] = sA[SWZ(r1, j0 + 4)];
            }
            #pragma unroll
            for (int nt = 0; nt < 8; nt++) {
                int r = wn + nt * 8 + g;
                uint32_t bh[2] = { sBh[SWZ(r, j0)], sBh[SWZ(r, j0 + 4)] };
                uint32_t bl[2] = { sBl[SWZ(r, j0)], sBl[SWZ(r, j0 + 4)] };
                mma16f(acc[0][nt], af[0], bh);
                mma16f(acc[1][nt], af[1], bh);
                mma16f(acc[0][nt], af[0], bl);
                mma16f(acc[1][nt], af[1], bl);
            }
        }
    }

    const size_t rbase = (size_t)blockIdx.y * 128 + wm;
    const int    cbase = blockIdx.x * 128 + wn;
    #pragma unroll
    for (int mt = 0; mt < 2; mt++) {
        #pragma unroll
        for (int half = 0; half < 2; half++) {
            size_t row = rbase + mt * 16 + half * 8 + g;
            size_t rowoff = row * (size_t)N;
            #pragma unroll
            for (int nt = 0; nt < 8; nt++) {
                int col = cbase + nt * 8 + 2 * t;
                float2 ov;
                ov.x = acc[mt][nt][half * 2 + 0];
                ov.y = acc[mt][nt][half * 2 + 1];
                *(float2*)(C + rowoff + col) = ov;
            }
        }
    }
}

// ============================================================================
// Flash attention, bf16x3 mma (R11-validated).
// ============================================================================
#define ASW(r,j)  ((r)*32 + ((j) ^ (((r)&7)<<2)))   // 64x32 b32 tile swizzle

__global__ void __launch_bounds__(128)
attn_mma(const __nv_bfloat16* __restrict__ qh, const __nv_bfloat16* __restrict__ ql,
         __nv_bfloat16* __restrict__ oh, __nv_bfloat16* __restrict__ ol)
{
    __shared__ uint32_t sk[2][2048];   // K planes  [kpos 64][d 32 b32] swizzled
    __shared__ uint32_t sv[2][2048];   // V^T planes [d 64][kpos 32 b32] swizzled

    const int qb  = blockIdx.x;
    const int bh  = blockIdx.y;
    const int bb  = bh >> 4, hh = bh & 15;
    const int tid = threadIdx.x;
    const int wq  = tid >> 5;
    const int lane = tid & 31;
    const int g = lane >> 2, t = lane & 3;
    const int row0 = qb * 64 + wq * 16 + g;
    const int row1 = row0 + 8;

    uint32_t qfh[4][4], qfl[4][4];
    {
        size_t b0 = ((size_t)(bb * TT + row0) * 3) * DD + hh * HDD;
        size_t b1 = ((size_t)(bb * TT + row1) * 3) * DD + hh * HDD;
        #pragma unroll
        for (int s = 0; s < 4; s++) {
            int c = 16 * s + 2 * t;
            qfh[s][0] = *(const uint32_t*)(qh + b0 + c);
            qfh[s][1] = *(const uint32_t*)(qh + b1 + c);
            qfh[s][2] = *(const uint32_t*)(qh + b0 + c + 8);
            qfh[s][3] = *(const uint32_t*)(qh + b1 + c + 8);
            qfl[s][0] = *(const uint32_t*)(ql + b0 + c);
            qfl[s][1] = *(const uint32_t*)(ql + b1 + c);
            qfl[s][2] = *(const uint32_t*)(ql + b0 + c + 8);
            qfl[s][3] = *(const uint32_t*)(ql + b1 + c + 8);
        }
    }

    float oacc[8][4] = {};
    float m0 = -1e30f, m1 = -1e30f, l0 = 0.f, l1 = 0.f;

    for (int kb = 0; kb <= qb; kb++) {
        __syncthreads();
        #pragma unroll
        for (int i = 0; i < 4; i++) {
            int lin = tid + i * 128;
            int r = lin >> 3, blk = lin & 7;
            uint32_t d = s2u(&sk[0][ASW(r, blk * 4)]);
            size_t src = ((size_t)(bb * TT + kb * 64 + r) * 3 + 1) * DD + hh * HDD + blk * 8;
            asm volatile("cp.async.cg.shared.global [%0], [%1], 16;" :: "r"(d),        "l"(qh + src));
            asm volatile("cp.async.cg.shared.global [%0], [%1], 16;" :: "r"(d + 8192), "l"(ql + src));
        }
        asm volatile("cp.async.commit_group;" ::: "memory");
        {
            int k  = tid & 63;
            int pl = tid >> 6;
            const __nv_bfloat16* vsrc = pl ? ql : qh;
            size_t vb = ((size_t)(bb * TT + kb * 64 + k) * 3 + 2) * DD + hh * HDD;
            char* base = (char*)sv[pl];
            #pragma unroll
            for (int j = 0; j < 32; j++) {
                uint32_t w = *(const uint32_t*)(vsrc + vb + 2 * j);
                uint32_t a0 = ASW(2*j,     k >> 1) * 4 + (k & 1) * 2;
                uint32_t a1 = ASW(2*j + 1, k >> 1) * 4 + (k & 1) * 2;
                *(uint16_t*)(base + a0) = (uint16_t)(w & 0xffff);
                *(uint16_t*)(base + a1) = (uint16_t)(w >> 16);
            }
        }
        asm volatile("cp.async.wait_group 0;" ::: "memory");
        __syncthreads();

        float sa[8][4] = {};
        #pragma unroll
        for (int s = 0; s < 4; s++) {
            #pragma unroll
            for (int nt = 0; nt < 8; nt++) {
                int r = nt * 8 + g;
                uint32_t bh2[2] = { sk[0][ASW(r, 8*s + t)], sk[0][ASW(r, 8*s + 4 + t)] };
                uint32_t bl2[2] = { sk[1][ASW(r, 8*s + t)], sk[1][ASW(r, 8*s + 4 + t)] };
                mma16(sa[nt], qfh[s], bh2);
                mma16(sa[nt], qfh[s], bl2);
                mma16(sa[nt], qfl[s], bh2);
            }
        }
        const bool diag = (kb == qb);
        #pragma unroll
        for (int nt = 0; nt < 8; nt++) {
            int colb = kb * 64 + nt * 8 + 2 * t;
            #pragma unroll
            for (int e = 0; e < 4; e++) {
                float v = sa[nt][e] * 0.125f;
                if (diag && (colb + (e & 1)) > ((e < 2) ? row0 : row1)) v = -1e30f;
                sa[nt][e] = v;
            }
        }
        float mn0 = m0, mn1 = m1;
        #pragma unroll
        for (int nt = 0; nt < 8; nt++) {
            mn0 = fmaxf(mn0, fmaxf(sa[nt][0], sa[nt][1]));
            mn1 = fmaxf(mn1, fmaxf(sa[nt][2], sa[nt][3]));
        }
        mn0 = fmaxf(mn0, __shfl_xor_sync(0xffffffffu, mn0, 1));
        mn0 = fmaxf(mn0, __shfl_xor_sync(0xffffffffu, mn0, 2));
        mn1 = fmaxf(mn1, __shfl_xor_sync(0xffffffffu, mn1, 1));
        mn1 = fmaxf(mn1, __shfl_xor_sync(0xffffffffu, mn1, 2));
        float al0 = __expf(m0 - mn0), al1 = __expf(m1 - mn1);
        m0 = mn0; m1 = mn1;
        float s0 = 0.f, s1 = 0.f;
        #pragma unroll
        for (int nt = 0; nt < 8; nt++) {
            sa[nt][0] = __expf(sa[nt][0] - m0);
            sa[nt][1] = __expf(sa[nt][1] - m0);
            sa[nt][2] = __expf(sa[nt][2] - m1);
            sa[nt][3] = __expf(sa[nt][3] - m1);
            s0 += sa[nt][0] + sa[nt][1];
            s1 += sa[nt][2] + sa[nt][3];
        }
        s0 += __shfl_xor_sync(0xffffffffu, s0, 1);
        s0 += __shfl_xor_sync(0xffffffffu, s0, 2);
        s1 += __shfl_xor_sync(0xffffffffu, s1, 1);
        s1 += __shfl_xor_sync(0xffffffffu, s1, 2);
        l0 = l0 * al0 + s0;
        l1 = l1 * al1 + s1;
        #pragma unroll
        for (int nt = 0; nt < 8; nt++) {
            oacc[nt][0] *= al0; oacc[nt][1] *= al0;
            oacc[nt][2] *= al1; oacc[nt][3] *= al1;
        }
        #pragma unroll
        for (int s = 0; s < 4; s++) {
            uint32_t ph[4], pl_[4];
            bsplit_pack(sa[2*s  ][0], sa[2*s  ][1], ph[0], pl_[0]);
            bsplit_pack(sa[2*s  ][2], sa[2*s  ][3], ph[1], pl_[1]);
            bsplit_pack(sa[2*s+1][0], sa[2*s+1][1], ph[2], pl_[2]);
            bsplit_pack(sa[2*s+1][2], sa[2*s+1][3], ph[3], pl_[3]);
            #pragma unroll
            for (int nt = 0; nt < 8; nt++) {
                int r = nt * 8 + g;
                uint32_t bh2[2] = { sv[0][ASW(r, 8*s + t)], sv[0][ASW(r, 8*s + 4 + t)] };
                uint32_t bl2[2] = { sv[1][ASW(r, 8*s + t)], sv[1][ASW(r, 8*s + 4 + t)] };
                mma16(oacc[nt], ph, bh2);
                mma16(oacc[nt], ph, bl2);
                mma16(oacc[nt], pl_, bh2);
            }
        }
    }

    float i0 = 1.f / l0, i1 = 1.f / l1;
    size_t ob0 = ((size_t)(bb * TT + row0) * NHH + hh) * HDD;
    size_t ob1 = ((size_t)(bb * TT + row1) * NHH + hh) * HDD;
    #pragma unroll
    for (int nt = 0; nt < 8; nt++) {
        int col = nt * 8 + 2 * t;
        uint32_t hp, lp;
        bsplit_pack(oacc[nt][0] * i0, oacc[nt][1] * i0, hp, lp);
        *(uint32_t*)(oh + ob0 + col) = hp;
        *(uint32_t*)(ol + ob0 + col) = lp;
        bsplit_pack(oacc[nt][2] * i1, oacc[nt][3] * i1, hp, lp);
        *(uint32_t*)(oh + ob1 + col) = hp;
        *(uint32_t*)(ol + ob1 + col) = lp;
    }
}

// ---------------- launch ----------------
extern "C" void kernel_launch(void* const* d_in, const int* in_sizes, int n_in,
                              void* d_out, int out_size)
{
    const int*   x      = (const int*)  d_in[0];
    const float* emb_w  = (const float*)d_in[1];
    const float* n1_w   = (const float*)d_in[2];
    const float* n2_w   = (const float*)d_in[3];
    const float* qkv_w  = (const float*)d_in[4];
    const float* qkv_b  = (const float*)d_in[5];
    const float* o_w    = (const float*)d_in[6];
    const float* o_b    = (const float*)d_in[7];
    const float* g_w    = (const float*)d_in[8];
    const float* g_b    = (const float*)d_in[9];
    const float* u_w    = (const float*)d_in[10];
    const float* u_b    = (const float*)d_in[11];
    const float* dn_w   = (const float*)d_in[12];
    const float* dn_b   = (const float*)d_in[13];
    const float* norm_w = (const float*)d_in[14];
    const float* head_w = (const float*)d_in[15];
    float* out = (float*)d_out;

    float *h, *fg;
    __nv_bfloat16 *nh, *nl, *qh3, *ql3, *ah, *al, *fgh, *fgl, *wh, *wl;
    cudaGetSymbolAddress((void**)&h,   g_h);
    cudaGetSymbolAddress((void**)&fg,  g_fg);
    cudaGetSymbolAddress((void**)&nh,  g_nh);
    cudaGetSymbolAddress((void**)&nl,  g_nl);
    cudaGetSymbolAddress((void**)&qh3, g_qh3);
    cudaGetSymbolAddress((void**)&ql3, g_ql3);
    cudaGetSymbolAddress((void**)&ah,  g_ah);
    cudaGetSymbolAddress((void**)&al,  g_al);
    cudaGetSymbolAddress((void**)&fgh, g_fgh);
    cudaGetSymbolAddress((void**)&fgl, g_fgl);
    cudaGetSymbolAddress((void**)&wh,  g_wh);
    cudaGetSymbolAddress((void**)&wl,  g_wl);

    cudaFuncSetAttribute(gemm_bf3<0>, cudaFuncAttributeMaxDynamicSharedMemorySize, GEMM_SMEM);
    cudaFuncSetAttribute(gemm_bf3<1>, cudaFuncAttributeMaxDynamicSharedMemorySize, GEMM_SMEM);
    cudaFuncSetAttribute(gemm_bf3<2>, cudaFuncAttributeMaxDynamicSharedMemorySize, GEMM_SMEM);
    cudaFuncSetAttribute(gemm_bf3<3>, cudaFuncAttributeMaxDynamicSharedMemorySize, GEMM_SMEM);
    cudaFuncSetAttribute(gemm_bf3<4>, cudaFuncAttributeMaxDynamicSharedMemorySize, GEMM_SMEM);
    cudaFuncSetAttribute(gemm_f16,    cudaFuncAttributeMaxDynamicSharedMemorySize, GEMM16_SMEM);

    auto wsplit = [&](const float* w, int elems) {
        int n4 = elems >> 2;
        wsplit_kernel<<<(n4 + 255) / 256, 256>>>(w, wh, wl, n4);
    };

    embed_kernel<<<MM, 256>>>(x, emb_w, h);

    for (int l = 0; l < NLL; l++) {
        // ---- attention block ----
        rmsnorm_kernel<<<MM, 256>>>(h, n1_w + (size_t)l * DD, nh, nl);
        wsplit(qkv_w + (size_t)l * 3 * DD * DD, 3 * DD * DD);
        gemm_bf3<4><<<dim3(3*DD/128, MM/128), 256, GEMM_SMEM>>>(
            nh, nl, wh, wl, qkv_b + (size_t)l * 3 * DD, nullptr, nullptr,
            qh3, ql3, 3*DD, DD);
        attn_mma<<<dim3(TT/64, BB*NHH), 128>>>(qh3, ql3, ah, al);
        wsplit(o_w + (size_t)l * DD * DD, DD * DD);
        gemm_bf3<1><<<dim3(DD/128, MM/128), 256, GEMM_SMEM>>>(
            ah, al, wh, wl, o_b + (size_t)l * DD, h, h,
            nullptr, nullptr, DD, DD);
        // ---- FFN block ----
        rmsnorm_kernel<<<MM, 256>>>(h, n2_w + (size_t)l * DD, nh, nl);
        wsplit(g_w + (size_t)l * FFD * DD, FFD * DD);
        gemm_bf3<2><<<dim3(FFD/128, MM/128), 256, GEMM_SMEM>>>(
            nh, nl, wh, wl, g_b + (size_t)l * FFD, nullptr, fg,
            nullptr, nullptr, FFD, DD);
        wsplit(u_w + (size_t)l * FFD * DD, FFD * DD);
        gemm_bf3<3><<<dim3(FFD/128, MM/128), 256, GEMM_SMEM>>>(
            nh, nl, wh, wl, u_b + (size_t)l * FFD, fg, nullptr,
            fgh, fgl, FFD, DD);
        wsplit(dn_w + (size_t)l * DD * FFD, DD * FFD);
        gemm_bf3<1><<<dim3(DD/128, MM/128), 256, GEMM_SMEM>>>(
            fgh, fgl, wh, wl, dn_b + (size_t)l * DD, h, h,
            nullptr, nullptr, DD, FFD);
    }

    // ---- head: fp16 2-term (output-only error ~1.4e-4) ----
    rmsnorm_f16_kernel<<<MM, 256>>>(h, norm_w, (__half*)nh);
    {
        int n4 = (VV * DD) >> 2;
        wsplit16_kernel<<<(n4 + 255) / 256, 256>>>(head_w, (__half*)wh, (__half*)wl, n4);
    }
    gemm_f16<<<dim3(VV/128, MM/128), 256, GEMM16_SMEM>>>(
        (const __half*)nh, (const __half*)wh, (const __half*)wl, out, VV, DD);
}

// round 14
// speedup vs baseline: 1.5426x; 1.5426x over previous
#include <cuda_runtime.h>
#include <cuda_bf16.h>
#include <cuda_fp16.h>
#include <math.h>
#include <stdint.h>

// ---------------- problem constants ----------------
#define BB   2
#define TT   2048
#define DD   1024
#define NHH  16
#define HDD  64
#define FFD  4096
#define NLL  2
#define VV   32000
#define MM   (BB*TT)          // 4096 rows
#define EPSF 1.1920929e-07f

// ---------------- scratch (device globals; no allocation allowed) ------------
__device__ float g_h  [MM * DD];        // residual stream (fp32)
__device__ float g_fg [MM * FFD];       // gate (silu applied, fp32)
__device__ __nv_bfloat16 g_nh [MM * DD];      // rmsnorm out hi/lo planes
__device__ __nv_bfloat16 g_nl [MM * DD];
__device__ __nv_bfloat16 g_qh3[MM * 3 * DD];  // qkv hi/lo planes
__device__ __nv_bfloat16 g_ql3[MM * 3 * DD];
__device__ __nv_bfloat16 g_ah [MM * DD];      // attention out hi/lo
__device__ __nv_bfloat16 g_al [MM * DD];
__device__ __nv_bfloat16 g_fgh[MM * FFD];     // gate*up hi/lo
__device__ __nv_bfloat16 g_fgl[MM * FFD];
__device__ __nv_bfloat16 g_wh [VV * DD];      // split weights (max = head)
__device__ __nv_bfloat16 g_wl [VV * DD];

// ---------------- small helpers ----------------
__device__ __forceinline__ uint32_t s2u(const void* p) {
    uint32_t a;
    asm("{ .reg .u64 t; cvta.to.shared.u64 t, %1; cvt.u32.u64 %0, t; }" : "=r"(a) : "l"(p));
    return a;
}
__device__ __forceinline__ void bsplit(float x, __nv_bfloat16& hi, __nv_bfloat16& lo) {
    hi = __float2bfloat16(x);
    lo = __float2bfloat16(x - __bfloat162float(hi));
}
__device__ __forceinline__ void bsplit_pack(float x, float y, uint32_t& hp, uint32_t& lp) {
    __nv_bfloat16 hx, lx, hy, ly;
    bsplit(x, hx, lx); bsplit(y, hy, ly);
    __nv_bfloat162 h2 = __halves2bfloat162(hx, hy);
    __nv_bfloat162 l2 = __halves2bfloat162(lx, ly);
    hp = *(uint32_t*)&h2; lp = *(uint32_t*)&l2;
}
__device__ __forceinline__ void hsplit_pack(float x, float y, uint32_t& hp, uint32_t& lp) {
    __half hx = __float2half_rn(x);
    __half hy = __float2half_rn(y);
    __half lx = __float2half_rn(x - __half2float(hx));
    __half ly = __float2half_rn(y - __half2float(hy));
    __half2 h2 = __halves2half2(hx, hy);
    __half2 l2 = __halves2half2(lx, ly);
    hp = *(uint32_t*)&h2; lp = *(uint32_t*)&l2;
}
__device__ __forceinline__ void mma16(float* c, const uint32_t* a, const uint32_t* b) {
    asm volatile(
        "mma.sync.aligned.m16n8k16.row.col.f32.bf16.bf16.f32 "
        "{%0,%1,%2,%3}, {%4,%5,%6,%7}, {%8,%9}, {%0,%1,%2,%3};"
        : "+f"(c[0]), "+f"(c[1]), "+f"(c[2]), "+f"(c[3])
        : "r"(a[0]), "r"(a[1]), "r"(a[2]), "r"(a[3]), "r"(b[0]), "r"(b[1]));
}
__device__ __forceinline__ void mma16f(float* c, const uint32_t* a, const uint32_t* b) {
    asm volatile(
        "mma.sync.aligned.m16n8k16.row.col.f32.f16.f16.f32 "
        "{%0,%1,%2,%3}, {%4,%5,%6,%7}, {%8,%9}, {%0,%1,%2,%3};"
        : "+f"(c[0]), "+f"(c[1]), "+f"(c[2]), "+f"(c[3])
        : "r"(a[0]), "r"(a[1]), "r"(a[2]), "r"(a[3]), "r"(b[0]), "r"(b[1]));
}

// ---------------- embedding gather ----------------
__global__ void embed_kernel(const int* __restrict__ x,
                             const float* __restrict__ emb,
                             float* __restrict__ h)
{
    int row = blockIdx.x;
    int t   = threadIdx.x;                // 256 threads, float4 each
    int id  = x[row];
    const float4* src = (const float4*)(emb + (size_t)id * DD);
    float4*       dst = (float4*)(h + (size_t)row * DD);
    dst[t] = src[t];
}

// ---------------- RMSNorm -> hi/lo bf16 planes ----------------
__global__ void rmsnorm_kernel(const float* __restrict__ in,
                               const float* __restrict__ w,
                               __nv_bfloat16* __restrict__ oh,
                               __nv_bfloat16* __restrict__ ol)
{
    int row = blockIdx.x;
    int t   = threadIdx.x;
    const float4* r4 = (const float4*)(in + (size_t)row * DD);
    float4 v = r4[t];
    float ss = v.x*v.x + v.y*v.y + v.z*v.z + v.w*v.w;
    #pragma unroll
    for (int o = 16; o; o >>= 1) ss += __shfl_xor_sync(0xffffffffu, ss, o);
    __shared__ float red[8];
    if ((t & 31) == 0) red[t >> 5] = ss;
    __syncthreads();
    __shared__ float scale_sh;
    if (t == 0) {
        float s = 0.f;
        #pragma unroll
        for (int i = 0; i < 8; i++) s += red[i];
        scale_sh = rsqrtf(s / (float)DD + EPSF);
    }
    __syncthreads();
    float sc = scale_sh;
    const float4* w4 = (const float4*)w;
    float4 wv = w4[t];
    uint32_t h0, l0, h1, l1;
    bsplit_pack(v.x * sc * wv.x, v.y * sc * wv.y, h0, l0);
    bsplit_pack(v.z * sc * wv.z, v.w * sc * wv.w, h1, l1);
    uint32_t* ph = (uint32_t*)(oh + (size_t)row * DD);
    uint32_t* pl = (uint32_t*)(ol + (size_t)row * DD);
    ph[2*t] = h0; ph[2*t+1] = h1;
    pl[2*t] = l0; pl[2*t+1] = l1;
}

// ---------------- RMSNorm -> single fp16 plane (final norm for head) ---------
__global__ void rmsnorm_f16_kernel(const float* __restrict__ in,
                                   const float* __restrict__ w,
                                   __half* __restrict__ oh)
{
    int row = blockIdx.x;
    int t   = threadIdx.x;
    const float4* r4 = (const float4*)(in + (size_t)row * DD);
    float4 v = r4[t];
    float ss = v.x*v.x + v.y*v.y + v.z*v.z + v.w*v.w;
    #pragma unroll
    for (int o = 16; o; o >>= 1) ss += __shfl_xor_sync(0xffffffffu, ss, o);
    __shared__ float red[8];
    if ((t & 31) == 0) red[t >> 5] = ss;
    __syncthreads();
    __shared__ float scale_sh;
    if (t == 0) {
        float s = 0.f;
        #pragma unroll
        for (int i = 0; i < 8; i++) s += red[i];
        scale_sh = rsqrtf(s / (float)DD + EPSF);
    }
    __syncthreads();
    float sc = scale_sh;
    const float4* w4 = (const float4*)w;
    float4 wv = w4[t];
    __half2 a = __halves2half2(__float2half_rn(v.x * sc * wv.x),
                               __float2half_rn(v.y * sc * wv.y));
    __half2 b = __halves2half2(__float2half_rn(v.z * sc * wv.z),
                               __float2half_rn(v.w * sc * wv.w));
    uint32_t* ph = (uint32_t*)(oh + (size_t)row * DD);
    ph[2*t]   = *(uint32_t*)&a;
    ph[2*t+1] = *(uint32_t*)&b;
}

// ---------------- weight split pass (fp32 -> hi/lo bf16 planes) --------------
__global__ void wsplit_kernel(const float* __restrict__ in,
                              __nv_bfloat16* __restrict__ oh,
                              __nv_bfloat16* __restrict__ ol, int n4)
{
    int i = blockIdx.x * blockDim.x + threadIdx.x;
    if (i < n4) {
        float4 v = ((const float4*)in)[i];
        uint32_t h0, l0, h1, l1;
        bsplit_pack(v.x, v.y, h0, l0);
        bsplit_pack(v.z, v.w, h1, l1);
        ((uint32_t*)oh)[2*i] = h0; ((uint32_t*)oh)[2*i+1] = h1;
        ((uint32_t*)ol)[2*i] = l0; ((uint32_t*)ol)[2*i+1] = l1;
    }
}

// ---------------- weight split pass (fp32 -> hi/lo fp16 planes) --------------
__global__ void wsplit16_kernel(const float* __restrict__ in,
                                __half* __restrict__ oh,
                                __half* __restrict__ ol, int n4)
{
    int i = blockIdx.x * blockDim.x + threadIdx.x;
    if (i < n4) {
        float4 v = ((const float4*)in)[i];
        uint32_t h0, l0, h1, l1;
        hsplit_pack(v.x, v.y, h0, l0);
        hsplit_pack(v.z, v.w, h1, l1);
        ((uint32_t*)oh)[2*i] = h0; ((uint32_t*)oh)[2*i+1] = h1;
        ((uint32_t*)ol)[2*i] = l0; ((uint32_t*)ol)[2*i+1] = l1;
    }
}

// ============================================================================
// bf16x3 GEMM (R11-validated mainloop, EXACT ordering): 
// C = (Ahi+Alo)(Whi+Wlo)^T (+bias)(+epi)
// CTA tile 128x128, K-chunk 32, 3-stage cp.async, 8 warps (4x2),
// warp tile 32(M)x64(N). XOR-swizzled smem, scalar LDS fragment loads.
// EPI: 0 bias | 1 bias+res | 2 bias+silu | 3 bias,*gate,split-out | 4 bias,split-out
// ============================================================================
#define SWZ(r,j)   ((r)*16 + ((j) ^ ((((r)>>1)&3)<<2)))
#define STG_U32    8192                        // 4 planes * 128 rows * 16 b32
#define GEMM_SMEM  (3 * STG_U32 * 4)           // 98304 bytes

template<int EPI>
__global__ void __launch_bounds__(256, 2)
gemm_bf3(const __nv_bfloat16* __restrict__ Ahi, const __nv_bfloat16* __restrict__ Alo,
         const __nv_bfloat16* __restrict__ Whi, const __nv_bfloat16* __restrict__ Wlo,
         const float* __restrict__ bias, const float* __restrict__ res,
         float* __restrict__ C,
         __nv_bfloat16* __restrict__ Ch, __nv_bfloat16* __restrict__ Cl,
         int N, int K)
{
    extern __shared__ uint32_t smu[];
    const int tid  = threadIdx.x;
    const int wid  = tid >> 5;
    const int lane = tid & 31;
    const int g    = lane >> 2;     // 0..7
    const int t    = lane & 3;      // 0..3
    const int wm   = (wid >> 1) * 32;   // warp M offset
    const int wn   = (wid & 1) * 64;    // warp N offset

    const __nv_bfloat16* Agh = Ahi + (size_t)blockIdx.y * 128 * K;
    const __nv_bfloat16* Agl = Alo + (size_t)blockIdx.y * 128 * K;
    const __nv_bfloat16* Wgh = Whi + (size_t)blockIdx.x * 128 * K;
    const __nv_bfloat16* Wgl = Wlo + (size_t)blockIdx.x * 128 * K;
    const int NC = K >> 5;              // chunks of K=32

    auto fill = [&](int c) {
        uint32_t* st = smu + (c % 3) * STG_U32;
        const __nv_bfloat16* s0 = Agh + c * 32;
        const __nv_bfloat16* s1 = Agl + c * 32;
        const __nv_bfloat16* s2 = Wgh + c * 32;
        const __nv_bfloat16* s3 = Wgl + c * 32;
        #pragma unroll
        for (int i = 0; i < 2; i++) {
            int lin = tid + i * 256;            // 0..511
            int r = lin >> 2, q = lin & 3;      // row, 16B-quarter
            uint32_t doff = SWZ(r, q * 4);      // u32 index within plane
            size_t soff = (size_t)r * K + q * 8;
            uint32_t d0 = s2u(st + doff);       // byte address; planes +8192B
            asm volatile("cp.async.cg.shared.global [%0], [%1], 16;" :: "r"(d0),         "l"(s0 + soff));
            asm volatile("cp.async.cg.shared.global [%0], [%1], 16;" :: "r"(d0 + 8192),  "l"(s1 + soff));
            asm volatile("cp.async.cg.shared.global [%0], [%1], 16;" :: "r"(d0 + 16384), "l"(s2 + soff));
            asm volatile("cp.async.cg.shared.global [%0], [%1], 16;" :: "r"(d0 + 24576), "l"(s3 + soff));
        }
    };

    float acc[2][8][4] = {};

    fill(0); asm volatile("cp.async.commit_group;" ::: "memory");
    fill(1); asm volatile("cp.async.commit_group;" ::: "memory");

    for (int c = 0; c < NC; c++) {
        asm volatile("cp.async.wait_group 1;" ::: "memory");
        __syncthreads();
        if (c + 2 < NC) fill(c + 2);
        asm volatile("cp.async.commit_group;" ::: "memory");

        const uint32_t* st  = smu + (c % 3) * STG_U32;
        const uint32_t* sAh = st;
        const uint32_t* sAl = st + 2048;
        const uint32_t* sBh = st + 4096;
        const uint32_t* sBl = st + 6144;

        #pragma unroll
        for (int ks = 0; ks < 2; ks++) {
            const int j0 = ks * 8 + t;
            uint32_t ah[2][4], al[2][4];
            #pragma unroll
            for (int mt = 0; mt < 2; mt++) {
                int r0 = wm + mt * 16 + g, r1 = r0 + 8;
                ah[mt][0] = sAh[SWZ(r0, j0)];     ah[mt][1] = sAh[SWZ(r1, j0)];
                ah[mt][2] = sAh[SWZ(r0, j0 + 4)]; ah[mt][3] = sAh[SWZ(r1, j0 + 4)];
                al[mt][0] = sAl[SWZ(r0, j0)];     al[mt][1] = sAl[SWZ(r1, j0)];
                al[mt][2] = sAl[SWZ(r0, j0 + 4)]; al[mt][3] = sAl[SWZ(r1, j0 + 4)];
            }
            #pragma unroll
            for (int nt = 0; nt < 8; nt++) {
                int r = wn + nt * 8 + g;
                uint32_t bh[2] = { sBh[SWZ(r, j0)], sBh[SWZ(r, j0 + 4)] };
                uint32_t bl[2] = { sBl[SWZ(r, j0)], sBl[SWZ(r, j0 + 4)] };
                #pragma unroll
                for (int mt = 0; mt < 2; mt++) {
                    mma16(acc[mt][nt], ah[mt], bh);
                    mma16(acc[mt][nt], ah[mt], bl);
                    mma16(acc[mt][nt], al[mt], bh);
                }
            }
        }
    }

    // ---- epilogue ----
    const size_t rbase = (size_t)blockIdx.y * 128 + wm;
    const int    cbase = blockIdx.x * 128 + wn;
    #pragma unroll
    for (int mt = 0; mt < 2; mt++) {
        #pragma unroll
        for (int half = 0; half < 2; half++) {
            size_t row = rbase + mt * 16 + half * 8 + g;
            size_t rowoff = row * (size_t)N;
            #pragma unroll
            for (int nt = 0; nt < 8; nt++) {
                int col = cbase + nt * 8 + 2 * t;
                float v0 = acc[mt][nt][half * 2 + 0];
                float v1 = acc[mt][nt][half * 2 + 1];
                if (bias) {
                    v0 += __ldg(bias + col);
                    v1 += __ldg(bias + col + 1);
                }
                if (EPI == 1) {
                    float2 rv = *(const float2*)(res + rowoff + col);
                    v0 += rv.x; v1 += rv.y;
                }
                if (EPI == 2) {
                    v0 = v0 / (1.f + __expf(-v0));
                    v1 = v1 / (1.f + __expf(-v1));
                }
                if (EPI == 3 || EPI == 4) {
                    if (EPI == 3) {
                        float2 gv = *(const float2*)(res + rowoff + col);
                        v0 *= gv.x; v1 *= gv.y;
                    }
                    uint32_t hp, lp;
                    bsplit_pack(v0, v1, hp, lp);
                    *(uint32_t*)(Ch + rowoff + col) = hp;
                    *(uint32_t*)(Cl + rowoff + col) = lp;
                } else {
                    float2 ov; ov.x = v0; ov.y = v1;
                    *(float2*)(C + rowoff + col) = ov;
                }
            }
        }
    }
}

// ============================================================================
// fp16 2-term GEMM (head only): C = Ah * (Wh+Wl)^T
// A is single fp16 plane; W split hi/lo fp16. 3 smem planes per stage.
// Same tiling as gemm_bf3; same-acc back-to-back MMA ordering (R11 style).
// ============================================================================
#define STG16_U32   6144                       // 3 planes * 2048 u32
#define GEMM16_SMEM (3 * STG16_U32 * 4)        // 73728 bytes

__global__ void __launch_bounds__(256, 2)
gemm_f16(const __half* __restrict__ A,
         const __half* __restrict__ Whi, const __half* __restrict__ Wlo,
         float* __restrict__ C, int N, int K)
{
    extern __shared__ uint32_t smu[];
    const int tid  = threadIdx.x;
    const int wid  = tid >> 5;
    const int lane = tid & 31;
    const int g    = lane >> 2;
    const int t    = lane & 3;
    const int wm   = (wid >> 1) * 32;
    const int wn   = (wid & 1) * 64;

    const __half* Ag  = A   + (size_t)blockIdx.y * 128 * K;
    const __half* Wgh = Whi + (size_t)blockIdx.x * 128 * K;
    const __half* Wgl = Wlo + (size_t)blockIdx.x * 128 * K;
    const int NC = K >> 5;

    auto fill = [&](int c) {
        uint32_t* st = smu + (c % 3) * STG16_U32;
        const __half* s0 = Ag  + c * 32;
        const __half* s1 = Wgh + c * 32;
        const __half* s2 = Wgl + c * 32;
        #pragma unroll
        for (int i = 0; i < 2; i++) {
            int lin = tid + i * 256;
            int r = lin >> 2, q = lin & 3;
            uint32_t doff = SWZ(r, q * 4);
            size_t soff = (size_t)r * K + q * 8;
            uint32_t d0 = s2u(st + doff);
            asm volatile("cp.async.cg.shared.global [%0], [%1], 16;" :: "r"(d0),         "l"(s0 + soff));
            asm volatile("cp.async.cg.shared.global [%0], [%1], 16;" :: "r"(d0 + 8192),  "l"(s1 + soff));
            asm volatile("cp.async.cg.shared.global [%0], [%1], 16;" :: "r"(d0 + 16384), "l"(s2 + soff));
        }
    };

    float acc[2][8][4] = {};

    fill(0); asm volatile("cp.async.commit_group;" ::: "memory");
    fill(1); asm volatile("cp.async.commit_group;" ::: "memory");

    for (int c = 0; c < NC; c++) {
        asm volatile("cp.async.wait_group 1;" ::: "memory");
        __syncthreads();
        if (c + 2 < NC) fill(c + 2);
        asm volatile("cp.async.commit_group;" ::: "memory");

        const uint32_t* st  = smu + (c % 3) * STG16_U32;
        const uint32_t* sA  = st;
        const uint32_t* sBh = st + 2048;
        const uint32_t* sBl = st + 4096;

        #pragma unroll
        for (int ks = 0; ks < 2; ks++) {
            const int j0 = ks * 8 + t;
            uint32_t af[2][4];
            #pragma unroll
            for (int mt = 0; mt < 2; mt++) {
                int r0 = wm + mt * 16 + g, r1 = r0 + 8;
                af[mt][0] = sA[SWZ(r0, j0)];     af[mt][1] = sA[SWZ(r1, j0)];
                af[mt][2] = sA[SWZ(r0, j0 + 4)]; af[mt][3] = sA[SWZ(r1, j0 + 4)];
            }
            #pragma unroll
            for (int nt = 0; nt < 8; nt++) {
                int r = wn + nt * 8 + g;
                uint32_t bh[2] = { sBh[SWZ(r, j0)], sBh[SWZ(r, j0 + 4)] };
                uint32_t bl[2] = { sBl[SWZ(r, j0)], sBl[SWZ(r, j0 + 4)] };
                #pragma unroll
                for (int mt = 0; mt < 2; mt++) {
                    mma16f(acc[mt][nt], af[mt], bh);
                    mma16f(acc[mt][nt], af[mt], bl);
                }
            }
        }
    }

    const size_t rbase = (size_t)blockIdx.y * 128 + wm;
    const int    cbase = blockIdx.x * 128 + wn;
    #pragma unroll
    for (int mt = 0; mt < 2; mt++) {
        #pragma unroll
        for (int half = 0; half < 2; half++) {
            size_t row = rbase + mt * 16 + half * 8 + g;
            size_t rowoff = row * (size_t)N;
            #pragma unroll
            for (int nt = 0; nt < 8; nt++) {
                int col = cbase + nt * 8 + 2 * t;
                float2 ov;
                ov.x = acc[mt][nt][half * 2 + 0];
                ov.y = acc[mt][nt][half * 2 + 1];
                *(float2*)(C + rowoff + col) = ov;
            }
        }
    }
}

// ============================================================================
// Flash attention, bf16x3 mma (R11-validated, unchanged).
// ============================================================================
#define ASW(r,j)  ((r)*32 + ((j) ^ (((r)&7)<<2)))   // 64x32 b32 tile swizzle

__global__ void __launch_bounds__(128)
attn_mma(const __nv_bfloat16* __restrict__ qh, const __nv_bfloat16* __restrict__ ql,
         __nv_bfloat16* __restrict__ oh, __nv_bfloat16* __restrict__ ol)
{
    __shared__ uint32_t sk[2][2048];   // K planes  [kpos 64][d 32 b32] swizzled
    __shared__ uint32_t sv[2][2048];   // V^T planes [d 64][kpos 32 b32] swizzled

    const int qb  = blockIdx.x;
    const int bh  = blockIdx.y;
    const int bb  = bh >> 4, hh = bh & 15;
    const int tid = threadIdx.x;
    const int wq  = tid >> 5;
    const int lane = tid & 31;
    const int g = lane >> 2, t = lane & 3;
    const int row0 = qb * 64 + wq * 16 + g;
    const int row1 = row0 + 8;

    uint32_t qfh[4][4], qfl[4][4];
    {
        size_t b0 = ((size_t)(bb * TT + row0) * 3) * DD + hh * HDD;
        size_t b1 = ((size_t)(bb * TT + row1) * 3) * DD + hh * HDD;
        #pragma unroll
        for (int s = 0; s < 4; s++) {
            int c = 16 * s + 2 * t;
            qfh[s][0] = *(const uint32_t*)(qh + b0 + c);
            qfh[s][1] = *(const uint32_t*)(qh + b1 + c);
            qfh[s][2] = *(const uint32_t*)(qh + b0 + c + 8);
            qfh[s][3] = *(const uint32_t*)(qh + b1 + c + 8);
            qfl[s][0] = *(const uint32_t*)(ql + b0 + c);
            qfl[s][1] = *(const uint32_t*)(ql + b1 + c);
            qfl[s][2] = *(const uint32_t*)(ql + b0 + c + 8);
            qfl[s][3] = *(const uint32_t*)(ql + b1 + c + 8);
        }
    }

    float oacc[8][4] = {};
    float m0 = -1e30f, m1 = -1e30f, l0 = 0.f, l1 = 0.f;

    for (int kb = 0; kb <= qb; kb++) {
        __syncthreads();
        #pragma unroll
        for (int i = 0; i < 4; i++) {
            int lin = tid + i * 128;
            int r = lin >> 3, blk = lin & 7;
            uint32_t d = s2u(&sk[0][ASW(r, blk * 4)]);
            size_t src = ((size_t)(bb * TT + kb * 64 + r) * 3 + 1) * DD + hh * HDD + blk * 8;
            asm volatile("cp.async.cg.shared.global [%0], [%1], 16;" :: "r"(d),        "l"(qh + src));
            asm volatile("cp.async.cg.shared.global [%0], [%1], 16;" :: "r"(d + 8192), "l"(ql + src));
        }
        asm volatile("cp.async.commit_group;" ::: "memory");
        {
            int k  = tid & 63;
            int pl = tid >> 6;
            const __nv_bfloat16* vsrc = pl ? ql : qh;
            size_t vb = ((size_t)(bb * TT + kb * 64 + k) * 3 + 2) * DD + hh * HDD;
            char* base = (char*)sv[pl];
            #pragma unroll
            for (int j = 0; j < 32; j++) {
                uint32_t w = *(const uint32_t*)(vsrc + vb + 2 * j);
                uint32_t a0 = ASW(2*j,     k >> 1) * 4 + (k & 1) * 2;
                uint32_t a1 = ASW(2*j + 1, k >> 1) * 4 + (k & 1) * 2;
                *(uint16_t*)(base + a0) = (uint16_t)(w & 0xffff);
                *(uint16_t*)(base + a1) = (uint16_t)(w >> 16);
            }
        }
        asm volatile("cp.async.wait_group 0;" ::: "memory");
        __syncthreads();

        float sa[8][4] = {};
        #pragma unroll
        for (int s = 0; s < 4; s++) {
            #pragma unroll
            for (int nt = 0; nt < 8; nt++) {
                int r = nt * 8 + g;
                uint32_t bh2[2] = { sk[0][ASW(r, 8*s + t)], sk[0][ASW(r, 8*s + 4 + t)] };
                uint32_t bl2[2] = { sk[1][ASW(r, 8*s + t)], sk[1][ASW(r, 8*s + 4 + t)] };
                mma16(sa[nt], qfh[s], bh2);
                mma16(sa[nt], qfh[s], bl2);
                mma16(sa[nt], qfl[s], bh2);
            }
        }
        const bool diag = (kb == qb);
        #pragma unroll
        for (int nt = 0; nt < 8; nt++) {
            int colb = kb * 64 + nt * 8 + 2 * t;
            #pragma unroll
            for (int e = 0; e < 4; e++) {
                float v = sa[nt][e] * 0.125f;
                if (diag && (colb + (e & 1)) > ((e < 2) ? row0 : row1)) v = -1e30f;
                sa[nt][e] = v;
            }
        }
        float mn0 = m0, mn1 = m1;
        #pragma unroll
        for (int nt = 0; nt < 8; nt++) {
            mn0 = fmaxf(mn0, fmaxf(sa[nt][0], sa[nt][1]));
            mn1 = fmaxf(mn1, fmaxf(sa[nt][2], sa[nt][3]));
        }
        mn0 = fmaxf(mn0, __shfl_xor_sync(0xffffffffu, mn0, 1));
        mn0 = fmaxf(mn0, __shfl_xor_sync(0xffffffffu, mn0, 2));
        mn1 = fmaxf(mn1, __shfl_xor_sync(0xffffffffu, mn1, 1));
        mn1 = fmaxf(mn1, __shfl_xor_sync(0xffffffffu, mn1, 2));
        float al0 = __expf(m0 - mn0), al1 = __expf(m1 - mn1);
        m0 = mn0; m1 = mn1;
        float s0 = 0.f, s1 = 0.f;
        #pragma unroll
        for (int nt = 0; nt < 8; nt++) {
            sa[nt][0] = __expf(sa[nt][0] - m0);
            sa[nt][1] = __expf(sa[nt][1] - m0);
            sa[nt][2] = __expf(sa[nt][2] - m1);
            sa[nt][3] = __expf(sa[nt][3] - m1);
            s0 += sa[nt][0] + sa[nt][1];
            s1 += sa[nt][2] + sa[nt][3];
        }
        s0 += __shfl_xor_sync(0xffffffffu, s0, 1);
        s0 += __shfl_xor_sync(0xffffffffu, s0, 2);
        s1 += __shfl_xor_sync(0xffffffffu, s1, 1);
        s1 += __shfl_xor_sync(0xffffffffu, s1, 2);
        l0 = l0 * al0 + s0;
        l1 = l1 * al1 + s1;
        #pragma unroll
        for (int nt = 0; nt < 8; nt++) {
            oacc[nt][0] *= al0; oacc[nt][1] *= al0;
            oacc[nt][2] *= al1; oacc[nt][3] *= al1;
        }
        #pragma unroll
        for (int s = 0; s < 4; s++) {
            uint32_t ph[4], pl_[4];
            bsplit_pack(sa[2*s  ][0], sa[2*s  ][1], ph[0], pl_[0]);
            bsplit_pack(sa[2*s  ][2], sa[2*s  ][3], ph[1], pl_[1]);
            bsplit_pack(sa[2*s+1][0], sa[2*s+1][1], ph[2], pl_[2]);
            bsplit_pack(sa[2*s+1][2], sa[2*s+1][3], ph[3], pl_[3]);
            #pragma unroll
            for (int nt = 0; nt < 8; nt++) {
                int r = nt * 8 + g;
                uint32_t bh2[2] = { sv[0][ASW(r, 8*s + t)], sv[0][ASW(r, 8*s + 4 + t)] };
                uint32_t bl2[2] = { sv[1][ASW(r, 8*s + t)], sv[1][ASW(r, 8*s + 4 + t)] };
                mma16(oacc[nt], ph, bh2);
                mma16(oacc[nt], ph, bl2);
                mma16(oacc[nt], pl_, bh2);
            }
        }
    }

    float i0 = 1.f / l0, i1 = 1.f / l1;
    size_t ob0 = ((size_t)(bb * TT + row0) * NHH + hh) * HDD;
    size_t ob1 = ((size_t)(bb * TT + row1) * NHH + hh) * HDD;
    #pragma unroll
    for (int nt = 0; nt < 8; nt++) {
        int col = nt * 8 + 2 * t;
        uint32_t hp, lp;
        bsplit_pack(oacc[nt][0] * i0, oacc[nt][1] * i0, hp, lp);
        *(uint32_t*)(oh + ob0 + col) = hp;
        *(uint32_t*)(ol + ob0 + col) = lp;
        bsplit_pack(oacc[nt][2] * i1, oacc[nt][3] * i1, hp, lp);
        *(uint32_t*)(oh + ob1 + col) = hp;
        *(uint32_t*)(ol + ob1 + col) = lp;
    }
}

// ---------------- launch ----------------
extern "C" void kernel_launch(void* const* d_in, const int* in_sizes, int n_in,
                              void* d_out, int out_size)
{
    const int*   x      = (const int*)  d_in[0];
    const float* emb_w  = (const float*)d_in[1];
    const float* n1_w   = (const float*)d_in[2];
    const float* n2_w   = (const float*)d_in[3];
    const float* qkv_w  = (const float*)d_in[4];
    const float* qkv_b  = (const float*)d_in[5];
    const float* o_w    = (const float*)d_in[6];
    const float* o_b    = (const float*)d_in[7];
    const float* g_w    = (const float*)d_in[8];
    const float* g_b    = (const float*)d_in[9];
    const float* u_w    = (const float*)d_in[10];
    const float* u_b    = (const float*)d_in[11];
    const float* dn_w   = (const float*)d_in[12];
    const float* dn_b   = (const float*)d_in[13];
    const float* norm_w = (const float*)d_in[14];
    const float* head_w = (const float*)d_in[15];
    float* out = (float*)d_out;

    float *h, *fg;
    __nv_bfloat16 *nh, *nl, *qh3, *ql3, *ah, *al, *fgh, *fgl, *wh, *wl;
    cudaGetSymbolAddress((void**)&h,   g_h);
    cudaGetSymbolAddress((void**)&fg,  g_fg);
    cudaGetSymbolAddress((void**)&nh,  g_nh);
    cudaGetSymbolAddress((void**)&nl,  g_nl);
    cudaGetSymbolAddress((void**)&qh3, g_qh3);
    cudaGetSymbolAddress((void**)&ql3, g_ql3);
    cudaGetSymbolAddress((void**)&ah,  g_ah);
    cudaGetSymbolAddress((void**)&al,  g_al);
    cudaGetSymbolAddress((void**)&fgh, g_fgh);
    cudaGetSymbolAddress((void**)&fgl, g_fgl);
    cudaGetSymbolAddress((void**)&wh,  g_wh);
    cudaGetSymbolAddress((void**)&wl,  g_wl);

    cudaFuncSetAttribute(gemm_bf3<0>, cudaFuncAttributeMaxDynamicSharedMemorySize, GEMM_SMEM);
    cudaFuncSetAttribute(gemm_bf3<1>, cudaFuncAttributeMaxDynamicSharedMemorySize, GEMM_SMEM);
    cudaFuncSetAttribute(gemm_bf3<2>, cudaFuncAttributeMaxDynamicSharedMemorySize, GEMM_SMEM);
    cudaFuncSetAttribute(gemm_bf3<3>, cudaFuncAttributeMaxDynamicSharedMemorySize, GEMM_SMEM);
    cudaFuncSetAttribute(gemm_bf3<4>, cudaFuncAttributeMaxDynamicSharedMemorySize, GEMM_SMEM);
    cudaFuncSetAttribute(gemm_f16,    cudaFuncAttributeMaxDynamicSharedMemorySize, GEMM16_SMEM);

    auto wsplit = [&](const float* w, int elems) {
        int n4 = elems >> 2;
        wsplit_kernel<<<(n4 + 255) / 256, 256>>>(w, wh, wl, n4);
    };

    embed_kernel<<<MM, 256>>>(x, emb_w, h);

    for (int l = 0; l < NLL; l++) {
        // ---- attention block ----
        rmsnorm_kernel<<<MM, 256>>>(h, n1_w + (size_t)l * DD, nh, nl);
        wsplit(qkv_w + (size_t)l * 3 * DD * DD, 3 * DD * DD);
        gemm_bf3<4><<<dim3(3*DD/128, MM/128), 256, GEMM_SMEM>>>(
            nh, nl, wh, wl, qkv_b + (size_t)l * 3 * DD, nullptr, nullptr,
            qh3, ql3, 3*DD, DD);
        attn_mma<<<dim3(TT/64, BB*NHH), 128>>>(qh3, ql3, ah, al);
        wsplit(o_w + (size_t)l * DD * DD, DD * DD);
        gemm_bf3<1><<<dim3(DD/128, MM/128), 256, GEMM_SMEM>>>(
            ah, al, wh, wl, o_b + (size_t)l * DD, h, h,
            nullptr, nullptr, DD, DD);
        // ---- FFN block ----
        rmsnorm_kernel<<<MM, 256>>>(h, n2_w + (size_t)l * DD, nh, nl);
        wsplit(g_w + (size_t)l * FFD * DD, FFD * DD);
        gemm_bf3<2><<<dim3(FFD/128, MM/128), 256, GEMM_SMEM>>>(
            nh, nl, wh, wl, g_b + (size_t)l * FFD, nullptr, fg,
            nullptr, nullptr, FFD, DD);
        wsplit(u_w + (size_t)l * FFD * DD, FFD * DD);
        gemm_bf3<3><<<dim3(FFD/128, MM/128), 256, GEMM_SMEM>>>(
            nh, nl, wh, wl, u_b + (size_t)l * FFD, fg, nullptr,
            fgh, fgl, FFD, DD);
        wsplit(dn_w + (size_t)l * DD * FFD, DD * FFD);
        gemm_bf3<1><<<dim3(DD/128, MM/128), 256, GEMM_SMEM>>>(
            fgh, fgl, wh, wl, dn_b + (size_t)l * DD, h, h,
            nullptr, nullptr, DD, FFD);
    }

    // ---- head: fp16 2-term (output-only error ~2e-4) ----
    rmsnorm_f16_kernel<<<MM, 256>>>(h, norm_w, (__half*)nh);
    {
        int n4 = (VV * DD) >> 2;
        wsplit16_kernel<<<(n4 + 255) / 256, 256>>>(head_w, (__half*)wh, (__half*)wl, n4);
    }
    gemm_f16<<<dim3(VV/128, MM/128), 256, GEMM16_SMEM>>>(
        (const __half*)nh, (const __half*)wh, (const __half*)wl, out, VV, DD);
}